// round 2
// baseline (speedup 1.0000x reference)
#include <cuda_runtime.h>
#include <cstdint>

// Problem constants (fixed by the dataset)
#define Bsz 4
#define Tsz 4096
#define Isz 1024
#define Esz 16
#define Ksz 512
#define Jsz 1024

// Tiling
#define BM 128
#define BN 128
#define BK 16
#define TM 8
#define TN 8
#define NTHREADS 256

__global__ __launch_bounds__(NTHREADS, 2)
void expert_gather_gemm_kernel(const float* __restrict__ X,
                               const int* __restrict__ ind,   // int32 (JAX x64 disabled)
                               const float* __restrict__ W,
                               float* __restrict__ Y) {
    const int be = blockIdx.z;          // 0..63
    const int b  = be >> 4;             // /E
    const int e  = be & 15;             // %E
    const int m0 = blockIdx.y * BM;     // row tile within K=512
    const int n0 = blockIdx.x * BN;     // col tile within J=1024

    __shared__ float As[BK][BM];        // A transposed: [k][m]
    __shared__ float Bs[BK][BN];        // B: [k][n]
    __shared__ int   rows[BM];          // gathered token indices

    const int tid = threadIdx.x;
    const int tx  = tid & 15;           // 0..15  (N direction)
    const int ty  = tid >> 4;           // 0..15  (M direction)

    // Gather the BM token indices this block needs
    if (tid < BM) {
        rows[tid] = ind[((size_t)b * Esz + e) * Ksz + m0 + tid];
    }
    __syncthreads();

    float acc[TM][TN];
    #pragma unroll
    for (int i = 0; i < TM; i++)
        #pragma unroll
        for (int j = 0; j < TN; j++)
            acc[i][j] = 0.0f;

    const float* __restrict__ Xb = X + (size_t)b * Tsz * Isz;
    const float* __restrict__ We = W + (size_t)e * Isz * Jsz;

    for (int k0 = 0; k0 < Isz; k0 += BK) {
        // ---- Load A tile: BM rows x BK k, gathered. 512 float4 / 256 threads = 2 each.
        #pragma unroll
        for (int l = tid; l < (BM * BK) / 4; l += NTHREADS) {
            const int row = l >> 2;            // 0..127
            const int kq  = (l & 3) << 2;      // 0,4,8,12
            const float4 v = *(const float4*)&Xb[(size_t)rows[row] * Isz + k0 + kq];
            As[kq + 0][row] = v.x;
            As[kq + 1][row] = v.y;
            As[kq + 2][row] = v.z;
            As[kq + 3][row] = v.w;
        }
        // ---- Load B tile: BK rows x BN cols. 512 float4 / 256 threads = 2 each.
        #pragma unroll
        for (int l = tid; l < (BK * BN) / 4; l += NTHREADS) {
            const int r  = l >> 5;             // 0..15
            const int cq = (l & 31) << 2;      // 0..124
            *(float4*)&Bs[r][cq] =
                *(const float4*)&We[(size_t)(k0 + r) * Jsz + n0 + cq];
        }
        __syncthreads();

        // ---- Compute
        #pragma unroll
        for (int kk = 0; kk < BK; kk++) {
            float a[TM], bb[TN];
            #pragma unroll
            for (int i = 0; i < TM; i++) a[i] = As[kk][ty * TM + i];
            #pragma unroll
            for (int j = 0; j < TN; j++) bb[j] = Bs[kk][tx * TN + j];
            #pragma unroll
            for (int i = 0; i < TM; i++)
                #pragma unroll
                for (int j = 0; j < TN; j++)
                    acc[i][j] = fmaf(a[i], bb[j], acc[i][j]);
        }
        __syncthreads();
    }

    // ---- Store 8x8 micro-tile, vectorized
    float* __restrict__ Yb = Y + (((size_t)be * Ksz + m0) * Jsz) + n0;
    #pragma unroll
    for (int i = 0; i < TM; i++) {
        const int row = ty * TM + i;
        #pragma unroll
        for (int j = 0; j < TN; j += 4) {
            float4 v = make_float4(acc[i][j], acc[i][j + 1], acc[i][j + 2], acc[i][j + 3]);
            *(float4*)&Yb[(size_t)row * Jsz + tx * TN + j] = v;
        }
    }
}

extern "C" void kernel_launch(void* const* d_in, const int* in_sizes, int n_in,
                              void* d_out, int out_size) {
    const float* X   = (const float*)d_in[0];
    const int*   ind = (const int*)d_in[1];
    const float* W   = (const float*)d_in[2];
    float*       Y   = (float*)d_out;

    dim3 grid(Jsz / BN, Ksz / BM, Bsz * Esz);   // (8, 4, 64)
    dim3 block(NTHREADS);
    expert_gather_gemm_kernel<<<grid, block>>>(X, ind, W, Y);
}

// round 4
// speedup vs baseline: 1.8700x; 1.8700x over previous
#include <cuda_runtime.h>
#include <cuda_bf16.h>
#include <cstdint>

#define Bsz 4
#define Tsz 4096
#define Isz 1024
#define Esz 16
#define Ksz 512
#define Jsz 1024

// ---------------- scratch: W transposed + bf16-split, [E][J][I] ----------------
__device__ __nv_bfloat16 g_WhiT[(size_t)Esz * Jsz * Isz];
__device__ __nv_bfloat16 g_WloT[(size_t)Esz * Jsz * Isz];

// ---------------- helpers ----------------
__device__ __forceinline__ uint32_t smem_u32(const void* p) {
    uint32_t a;
    asm("{ .reg .u64 t; cvta.to.shared.u64 t, %1; cvt.u32.u64 %0, t; }" : "=r"(a) : "l"(p));
    return a;
}
// 64B rows of 4x16B chunks; chunk xor'd by ((row>>1)&3): conflict-free for both
// STS patterns and ldmatrix row-phases (verified mod-128 bank mapping).
__device__ __forceinline__ uint32_t swzoff(int row, int c) {
    return (uint32_t)(row * 64 + ((c ^ ((row >> 1) & 3)) * 16));
}
__device__ __forceinline__ void ldsm4(uint32_t* r, uint32_t addr) {
    asm volatile("ldmatrix.sync.aligned.m8n8.x4.shared.b16 {%0,%1,%2,%3}, [%4];"
                 : "=r"(r[0]), "=r"(r[1]), "=r"(r[2]), "=r"(r[3]) : "r"(addr));
}
__device__ __forceinline__ void mma16816(float* d, const uint32_t* a, const uint32_t* b) {
    asm volatile("mma.sync.aligned.m16n8k16.row.col.f32.bf16.bf16.f32 "
                 "{%0,%1,%2,%3},{%4,%5,%6,%7},{%8,%9},{%0,%1,%2,%3};"
                 : "+f"(d[0]), "+f"(d[1]), "+f"(d[2]), "+f"(d[3])
                 : "r"(a[0]), "r"(a[1]), "r"(a[2]), "r"(a[3]), "r"(b[0]), "r"(b[1]));
}
__device__ __forceinline__ void cpasync16(uint32_t dst, const void* src) {
    asm volatile("cp.async.cg.shared.global [%0], [%1], 16;" :: "r"(dst), "l"(src));
}
__device__ __forceinline__ void sts4(uint32_t addr, uint32_t a, uint32_t b, uint32_t c, uint32_t d) {
    asm volatile("st.shared.v4.b32 [%0], {%1,%2,%3,%4};" :: "r"(addr), "r"(a), "r"(b), "r"(c), "r"(d));
}

// ---------------- pre-pass: W [E][I][J] fp32 -> W^T hi/lo bf16 [E][J][I] ----------------
__global__ void w_split_transpose(const float* __restrict__ W) {
    __shared__ float tile[32][33];
    const int e = blockIdx.z;
    const int i0 = blockIdx.y * 32, j0 = blockIdx.x * 32;
    const int tx = threadIdx.x, ty = threadIdx.y;   // 32 x 8
    const float* Wp = W + ((size_t)e * Isz + i0) * Jsz + j0;
    #pragma unroll
    for (int r = 0; r < 4; r++)
        tile[ty + 8 * r][tx] = Wp[(size_t)(ty + 8 * r) * Jsz + tx];
    __syncthreads();
    const size_t ob = ((size_t)e * Jsz + j0) * Isz + i0;
    #pragma unroll
    for (int r = 0; r < 4; r++) {
        const int j = ty + 8 * r;
        const float x = tile[tx][j];
        const __nv_bfloat16 h = __float2bfloat16(x);
        const float hf = __bfloat162float(h);
        const __nv_bfloat16 l = __float2bfloat16(x - hf);
        g_WhiT[ob + (size_t)j * Isz + tx] = h;
        g_WloT[ob + (size_t)j * Isz + tx] = l;
    }
}

// ---------------- main: 128x128 tile, bf16x3 via mma.sync ----------------
#define NT 256
#define STAGE 32768
// per stage: A_HI @0 (8KB), A_LO @8192, B_HI @16384, B_LO @24576
#define SMEM_BYTES (2 * STAGE + 512)

__global__ __launch_bounds__(NT, 1)
void moe_gemm(const float* __restrict__ X, const int* __restrict__ ind,
              float* __restrict__ Y) {
    extern __shared__ char sm[];
    const uint32_t sbase = smem_u32(sm);
    int* rows = (int*)(sm + 2 * STAGE);

    const int tid = threadIdx.x;
    const int be = blockIdx.z, b = be >> 4, e = be & 15;
    const int m0 = blockIdx.y * 128, n0 = blockIdx.x * 128;

    if (tid < 128) rows[tid] = ind[((size_t)b * Esz + e) * Ksz + m0 + tid];
    __syncthreads();

    // ---- producer mappings
    const int am  = tid & 127;
    const int akb = (tid >> 7) * 16;                  // 0 or 16 (k within 32-chunk)
    const float* xrow = X + (size_t)b * Tsz * Isz + (size_t)rows[am] * Isz + akb;
    const uint32_t offA0 = swzoff(am, akb >> 3);
    const uint32_t offA1 = swzoff(am, (akb >> 3) + 1);

    const int bn  = tid >> 1;
    const int bc0 = (tid & 1) * 2;
    const __nv_bfloat16* whsrc = g_WhiT + ((size_t)e * Jsz + n0 + bn) * Isz + bc0 * 8;
    const __nv_bfloat16* wlsrc = g_WloT + ((size_t)e * Jsz + n0 + bn) * Isz + bc0 * 8;
    const uint32_t offB0 = swzoff(bn, bc0);
    const uint32_t offB1 = swzoff(bn, bc0 + 1);

    // ---- consumer mappings (warp tile 32x64)
    const int lane = tid & 31, w = tid >> 5;
    const int wm = (w & 3) * 32, wn = (w >> 2) * 64;
    uint32_t loffA[2], loffB[4];
    {
        const int chiA = lane >> 4;
        #pragma unroll
        for (int mt = 0; mt < 2; ++mt) {
            const int rowA = wm + mt * 16 + (lane & 7) + ((lane >> 3) & 1) * 8;
            loffA[mt] = swzoff(rowA, chiA);
        }
        const int chiB = (lane >> 3) & 1;
        #pragma unroll
        for (int ng = 0; ng < 4; ++ng) {
            const int rowB = wn + ng * 16 + (lane & 7) + ((lane >> 4) & 1) * 8;
            loffB[ng] = swzoff(rowB, chiB);
        }
    }

    float acc[2][8][4];
    #pragma unroll
    for (int i = 0; i < 2; ++i)
        #pragma unroll
        for (int j = 0; j < 8; ++j)
            #pragma unroll
            for (int q = 0; q < 4; ++q) acc[i][j][q] = 0.0f;

    float fa[16];
    // ---- prologue: chunk 0
    {
        const float4* p = (const float4*)xrow;
        #pragma unroll
        for (int q = 0; q < 4; ++q) ((float4*)fa)[q] = p[q];
        cpasync16(sbase + 16384 + offB0, whsrc);
        cpasync16(sbase + 16384 + offB1, whsrc + 8);
        cpasync16(sbase + 24576 + offB0, wlsrc);
        cpasync16(sbase + 24576 + offB1, wlsrc + 8);
        asm volatile("cp.async.commit_group;" ::: "memory");
    }

    for (int c = 0; c < 32; ++c) {
        const uint32_t stg = sbase + (uint32_t)(c & 1) * STAGE;

        // ---- STS A(c): fp32 -> bf16 hi/lo
        uint32_t h[8], l[8];
        #pragma unroll
        for (int i = 0; i < 8; ++i) {
            __nv_bfloat162 hh = __floats2bfloat162_rn(fa[2 * i], fa[2 * i + 1]);
            const float2 hf = __bfloat1622float2(hh);
            __nv_bfloat162 ll = __floats2bfloat162_rn(fa[2 * i] - hf.x, fa[2 * i + 1] - hf.y);
            h[i] = *(uint32_t*)&hh;
            l[i] = *(uint32_t*)&ll;
        }
        sts4(stg + offA0, h[0], h[1], h[2], h[3]);
        sts4(stg + offA1, h[4], h[5], h[6], h[7]);
        sts4(stg + 8192 + offA0, l[0], l[1], l[2], l[3]);
        sts4(stg + 8192 + offA1, l[4], l[5], l[6], l[7]);

        if (c < 31) {
            const float4* p = (const float4*)(xrow + (c + 1) * 32);
            #pragma unroll
            for (int q = 0; q < 4; ++q) ((float4*)fa)[q] = p[q];
            const uint32_t nstg = sbase + (uint32_t)((c + 1) & 1) * STAGE;
            const int k0 = (c + 1) * 32;
            cpasync16(nstg + 16384 + offB0, whsrc + k0);
            cpasync16(nstg + 16384 + offB1, whsrc + k0 + 8);
            cpasync16(nstg + 24576 + offB0, wlsrc + k0);
            cpasync16(nstg + 24576 + offB1, wlsrc + k0 + 8);
            asm volatile("cp.async.commit_group;" ::: "memory");
            asm volatile("cp.async.wait_group 1;" ::: "memory");
        } else {
            asm volatile("cp.async.wait_group 0;" ::: "memory");
        }
        __syncthreads();

        // ---- compute: 2 ksteps x (4 ldA + 8 ldB + 48 mma)
        #pragma unroll
        for (int ks = 0; ks < 2; ++ks) {
            const uint32_t kx = (uint32_t)ks << 5;
            uint32_t ah[2][4], al_[2][4], bh[4][4], bl[4][4];
            #pragma unroll
            for (int mt = 0; mt < 2; ++mt) {
                ldsm4(ah[mt],  stg +        (loffA[mt] ^ kx));
                ldsm4(al_[mt], stg + 8192 + (loffA[mt] ^ kx));
            }
            #pragma unroll
            for (int ng = 0; ng < 4; ++ng) {
                ldsm4(bh[ng], stg + 16384 + (loffB[ng] ^ kx));
                ldsm4(bl[ng], stg + 24576 + (loffB[ng] ^ kx));
            }
            #pragma unroll
            for (int mt = 0; mt < 2; ++mt)
                #pragma unroll
                for (int ng = 0; ng < 4; ++ng) {
                    mma16816(acc[mt][2 * ng],     ah[mt],  bh[ng]);
                    mma16816(acc[mt][2 * ng + 1], ah[mt],  bh[ng] + 2);
                    mma16816(acc[mt][2 * ng],     ah[mt],  bl[ng]);
                    mma16816(acc[mt][2 * ng + 1], ah[mt],  bl[ng] + 2);
                    mma16816(acc[mt][2 * ng],     al_[mt], bh[ng]);
                    mma16816(acc[mt][2 * ng + 1], al_[mt], bh[ng] + 2);
                }
        }
        __syncthreads();
    }

    // ---- epilogue
    float* Yb = Y + ((size_t)be * Ksz + m0) * Jsz + n0;
    #pragma unroll
    for (int mt = 0; mt < 2; ++mt) {
        const int row = wm + mt * 16 + (lane >> 2);
        #pragma unroll
        for (int j = 0; j < 8; ++j) {
            const int col = wn + j * 8 + (lane & 3) * 2;
            float2 v0 = make_float2(acc[mt][j][0], acc[mt][j][1]);
            float2 v1 = make_float2(acc[mt][j][2], acc[mt][j][3]);
            *(float2*)&Yb[(size_t)row * Jsz + col] = v0;
            *(float2*)&Yb[(size_t)(row + 8) * Jsz + col] = v1;
        }
    }
}

// ---------------- launch ----------------
extern "C" void kernel_launch(void* const* d_in, const int* in_sizes, int n_in,
                              void* d_out, int out_size) {
    const float* X   = (const float*)d_in[0];
    const int*   ind = (const int*)d_in[1];
    const float* W   = (const float*)d_in[2];
    float*       Y   = (float*)d_out;

    cudaFuncSetAttribute(moe_gemm, cudaFuncAttributeMaxDynamicSharedMemorySize, SMEM_BYTES);

    dim3 pgrid(Jsz / 32, Isz / 32, Esz);
    w_split_transpose<<<pgrid, dim3(32, 8)>>>(W);

    dim3 grid(Jsz / 128, Ksz / 128, Bsz * Esz);   // (8, 4, 64) = 2048 CTAs
    moe_gemm<<<grid, NT, SMEM_BYTES>>>(X, ind, Y);
}

// round 5
// speedup vs baseline: 2.3369x; 1.2497x over previous
#include <cuda_runtime.h>
#include <cuda_bf16.h>
#include <cstdint>

#define Bsz 4
#define Tsz 4096
#define Isz 1024
#define Esz 16
#define Ksz 512
#define Jsz 1024

// ---------------- scratch: pre-split operands ----------------
__device__ __nv_bfloat16 g_WhiT[(size_t)Esz * Jsz * Isz];   // W^T [E][J][I]
__device__ __nv_bfloat16 g_WloT[(size_t)Esz * Jsz * Isz];
__device__ __nv_bfloat16 g_Xhi[(size_t)Bsz * Tsz * Isz];    // X   [B][T][I]
__device__ __nv_bfloat16 g_Xlo[(size_t)Bsz * Tsz * Isz];

// ---------------- helpers ----------------
__device__ __forceinline__ uint32_t smem_u32(const void* p) {
    uint32_t a;
    asm("{ .reg .u64 t; cvta.to.shared.u64 t, %1; cvt.u32.u64 %0, t; }" : "=r"(a) : "l"(p));
    return a;
}
// 64B rows of 4x16B chunks; chunk xor'd by ((row>>1)&3): conflict-free STS/ldsm.
__device__ __forceinline__ uint32_t swzoff(int row, int c) {
    return (uint32_t)(row * 64 + ((c ^ ((row >> 1) & 3)) * 16));
}
__device__ __forceinline__ void ldsm4(uint32_t* r, uint32_t addr) {
    asm volatile("ldmatrix.sync.aligned.m8n8.x4.shared.b16 {%0,%1,%2,%3}, [%4];"
                 : "=r"(r[0]), "=r"(r[1]), "=r"(r[2]), "=r"(r[3]) : "r"(addr));
}
__device__ __forceinline__ void mma16816(float* d, const uint32_t* a, const uint32_t* b) {
    asm volatile("mma.sync.aligned.m16n8k16.row.col.f32.bf16.bf16.f32 "
                 "{%0,%1,%2,%3},{%4,%5,%6,%7},{%8,%9},{%0,%1,%2,%3};"
                 : "+f"(d[0]), "+f"(d[1]), "+f"(d[2]), "+f"(d[3])
                 : "r"(a[0]), "r"(a[1]), "r"(a[2]), "r"(a[3]), "r"(b[0]), "r"(b[1]));
}
__device__ __forceinline__ void cpasync16(uint32_t dst, const void* src) {
    asm volatile("cp.async.cg.shared.global [%0], [%1], 16;" :: "r"(dst), "l"(src));
}

// ---------------- pre-pass 1: W [E][I][J] fp32 -> W^T hi/lo bf16 [E][J][I] ----------------
__global__ void w_split_transpose(const float* __restrict__ W) {
    __shared__ float tile[32][33];
    const int e = blockIdx.z;
    const int i0 = blockIdx.y * 32, j0 = blockIdx.x * 32;
    const int tx = threadIdx.x, ty = threadIdx.y;   // 32 x 8
    const float* Wp = W + ((size_t)e * Isz + i0) * Jsz + j0;
    #pragma unroll
    for (int r = 0; r < 4; r++)
        tile[ty + 8 * r][tx] = Wp[(size_t)(ty + 8 * r) * Jsz + tx];
    __syncthreads();
    const size_t ob = ((size_t)e * Jsz + j0) * Isz + i0;
    #pragma unroll
    for (int r = 0; r < 4; r++) {
        const int j = ty + 8 * r;
        const float x = tile[tx][j];
        const __nv_bfloat16 h = __float2bfloat16(x);
        const float hf = __bfloat162float(h);
        const __nv_bfloat16 l = __float2bfloat16(x - hf);
        g_WhiT[ob + (size_t)j * Isz + tx] = h;
        g_WloT[ob + (size_t)j * Isz + tx] = l;
    }
}

// ---------------- pre-pass 2: X fp32 -> hi/lo bf16 (same layout) ----------------
__global__ void x_split(const float* __restrict__ X) {
    const size_t i = ((size_t)blockIdx.x * blockDim.x + threadIdx.x) * 4;
    const float4 v = *(const float4*)(X + i);
    __nv_bfloat162 h01 = __floats2bfloat162_rn(v.x, v.y);
    __nv_bfloat162 h23 = __floats2bfloat162_rn(v.z, v.w);
    const float2 f01 = __bfloat1622float2(h01);
    const float2 f23 = __bfloat1622float2(h23);
    __nv_bfloat162 l01 = __floats2bfloat162_rn(v.x - f01.x, v.y - f01.y);
    __nv_bfloat162 l23 = __floats2bfloat162_rn(v.z - f23.x, v.w - f23.y);
    uint2 hh = make_uint2(*(uint32_t*)&h01, *(uint32_t*)&h23);
    uint2 ll = make_uint2(*(uint32_t*)&l01, *(uint32_t*)&l23);
    *(uint2*)(g_Xhi + i) = hh;
    *(uint2*)(g_Xlo + i) = ll;
}

// ---------------- main: 128x128 tile, bf16x3, 4-stage cp.async ----------------
#define NT 256
#define STAGE 32768
#define NSTG 4
// per stage: A_HI @0 (8KB), A_LO @8192, B_HI @16384, B_LO @24576
#define SMEM_BYTES (NSTG * STAGE + 512)

__global__ __launch_bounds__(NT, 1)
void moe_gemm(const int* __restrict__ ind, float* __restrict__ Y) {
    extern __shared__ char sm[];
    const uint32_t sbase = smem_u32(sm);
    int* rows = (int*)(sm + NSTG * STAGE);

    const int tid = threadIdx.x;
    const int be = blockIdx.z, b = be >> 4, e = be & 15;
    const int m0 = blockIdx.y * 128, n0 = blockIdx.x * 128;

    if (tid < 128) rows[tid] = ind[((size_t)b * Esz + e) * Ksz + m0 + tid];
    __syncthreads();

    // ---- producer mapping: thread t -> row t>>1, 16B chunks {2(t&1), 2(t&1)+1}
    const int prow = tid >> 1;
    const int pc   = (tid & 1) * 2;
    const uint32_t off0 = swzoff(prow, pc);
    const uint32_t off1 = swzoff(prow, pc + 1);
    const size_t xoff = ((size_t)b * Tsz + rows[prow]) * Isz + pc * 8;
    const __nv_bfloat16* xh = g_Xhi + xoff;
    const __nv_bfloat16* xl = g_Xlo + xoff;
    const size_t woff = ((size_t)e * Jsz + n0 + prow) * Isz + pc * 8;
    const __nv_bfloat16* wh = g_WhiT + woff;
    const __nv_bfloat16* wl = g_WloT + woff;

    // ---- consumer mapping (warp tile 32x64)
    const int lane = tid & 31, w = tid >> 5;
    const int wm = (w & 3) * 32, wn = (w >> 2) * 64;
    uint32_t loffA[2], loffB[4];
    {
        const int chiA = lane >> 4;
        #pragma unroll
        for (int mt = 0; mt < 2; ++mt) {
            const int rowA = wm + mt * 16 + (lane & 7) + ((lane >> 3) & 1) * 8;
            loffA[mt] = swzoff(rowA, chiA);
        }
        const int chiB = (lane >> 3) & 1;
        #pragma unroll
        for (int ng = 0; ng < 4; ++ng) {
            const int rowB = wn + ng * 16 + (lane & 7) + ((lane >> 4) & 1) * 8;
            loffB[ng] = swzoff(rowB, chiB);
        }
    }

    float acc[2][8][4];
    #pragma unroll
    for (int i = 0; i < 2; ++i)
        #pragma unroll
        for (int j = 0; j < 8; ++j)
            #pragma unroll
            for (int q = 0; q < 4; ++q) acc[i][j][q] = 0.0f;

    // ---- issue loads for one stage
    auto issue = [&](int c) {
        const uint32_t stg = sbase + (uint32_t)(c & (NSTG - 1)) * STAGE;
        const int k0 = c * 32;
        cpasync16(stg + off0,         xh + k0);
        cpasync16(stg + off1,         xh + k0 + 8);
        cpasync16(stg + 8192  + off0, xl + k0);
        cpasync16(stg + 8192  + off1, xl + k0 + 8);
        cpasync16(stg + 16384 + off0, wh + k0);
        cpasync16(stg + 16384 + off1, wh + k0 + 8);
        cpasync16(stg + 24576 + off0, wl + k0);
        cpasync16(stg + 24576 + off1, wl + k0 + 8);
    };

    // ---- prologue: stages 0..2, one group each
    #pragma unroll
    for (int s = 0; s < NSTG - 1; ++s) {
        issue(s);
        asm volatile("cp.async.commit_group;" ::: "memory");
    }

    for (int c = 0; c < 32; ++c) {
        asm volatile("cp.async.wait_group %0;" :: "n"(NSTG - 2) : "memory");
        __syncthreads();

        // issue next stage (into the buffer freed by iteration c-1)
        if (c + NSTG - 1 < 32) issue(c + NSTG - 1);
        asm volatile("cp.async.commit_group;" ::: "memory");  // unconditional: keeps group count fixed

        const uint32_t stg = sbase + (uint32_t)(c & (NSTG - 1)) * STAGE;

        #pragma unroll
        for (int ks = 0; ks < 2; ++ks) {
            const uint32_t kx = (uint32_t)ks << 5;
            uint32_t ah[2][4], al_[2][4], bh[4][4], bl[4][4];
            #pragma unroll
            for (int mt = 0; mt < 2; ++mt) {
                ldsm4(ah[mt],  stg +        (loffA[mt] ^ kx));
                ldsm4(al_[mt], stg + 8192 + (loffA[mt] ^ kx));
            }
            #pragma unroll
            for (int ng = 0; ng < 4; ++ng) {
                ldsm4(bh[ng], stg + 16384 + (loffB[ng] ^ kx));
                ldsm4(bl[ng], stg + 24576 + (loffB[ng] ^ kx));
            }
            #pragma unroll
            for (int mt = 0; mt < 2; ++mt)
                #pragma unroll
                for (int ng = 0; ng < 4; ++ng) {
                    mma16816(acc[mt][2 * ng],     ah[mt],  bh[ng]);
                    mma16816(acc[mt][2 * ng + 1], ah[mt],  bh[ng] + 2);
                    mma16816(acc[mt][2 * ng],     ah[mt],  bl[ng]);
                    mma16816(acc[mt][2 * ng + 1], ah[mt],  bl[ng] + 2);
                    mma16816(acc[mt][2 * ng],     al_[mt], bh[ng]);
                    mma16816(acc[mt][2 * ng + 1], al_[mt], bh[ng] + 2);
                }
        }
        __syncthreads();
    }

    // ---- epilogue
    float* Yb = Y + ((size_t)be * Ksz + m0) * Jsz + n0;
    #pragma unroll
    for (int mt = 0; mt < 2; ++mt) {
        const int row = wm + mt * 16 + (lane >> 2);
        #pragma unroll
        for (int j = 0; j < 8; ++j) {
            const int col = wn + j * 8 + (lane & 3) * 2;
            float2 v0 = make_float2(acc[mt][j][0], acc[mt][j][1]);
            float2 v1 = make_float2(acc[mt][j][2], acc[mt][j][3]);
            *(float2*)&Yb[(size_t)row * Jsz + col] = v0;
            *(float2*)&Yb[(size_t)(row + 8) * Jsz + col] = v1;
        }
    }
}

// ---------------- launch ----------------
extern "C" void kernel_launch(void* const* d_in, const int* in_sizes, int n_in,
                              void* d_out, int out_size) {
    const float* X   = (const float*)d_in[0];
    const int*   ind = (const int*)d_in[1];
    const float* W   = (const float*)d_in[2];
    float*       Y   = (float*)d_out;

    cudaFuncSetAttribute(moe_gemm, cudaFuncAttributeMaxDynamicSharedMemorySize, SMEM_BYTES);

    dim3 pgrid(Jsz / 32, Isz / 32, Esz);
    w_split_transpose<<<pgrid, dim3(32, 8)>>>(W);
    x_split<<<(Bsz * Tsz * Isz) / (256 * 4), 256>>>(X);

    dim3 grid(Jsz / 128, Ksz / 128, Bsz * Esz);   // (8, 4, 64) = 2048 CTAs
    moe_gemm<<<grid, NT, SMEM_BYTES>>>(ind, Y);
}